// round 15
// baseline (speedup 1.0000x reference)
#include <cuda_runtime.h>
#include <cuda_fp16.h>

#define N_NODES 80000
#define N_EDGES 1280000
#define IN_CH 128
#define HID 64
#define OUT_CH 32

#define SCAN_BLK 512
#define N_SCAN_BLOCKS ((N_NODES + SCAN_BLK - 1) / SCAN_BLK)   // 157

__device__ __align__(256) float  g_dinv[N_NODES];
__device__ __align__(256) int    g_cnt [N_NODES];
__device__ __align__(256) int    g_offs[N_NODES + 1];
__device__ __align__(256) int    g_cursor[N_NODES];
__device__ __align__(256) int    g_csr [N_EDGES];
__device__ __align__(256) int    g_bagg [N_SCAN_BLOCKS];
__device__ __align__(256) int    g_bpre [N_SCAN_BLOCKS];
__device__ __align__(256) int    g_bflag[N_SCAN_BLOCKS];
__device__ __align__(256) __half g_h1s [(size_t)N_NODES * HID];     // fp16: dinv*(x@W1)
__device__ __align__(256) __half g_h2s [(size_t)N_NODES * OUT_CH];  // fp16: dinv*(out1@W2)

// ---------------- CSR build (proven R12) ----------------

__global__ void k_cnt(const int* __restrict__ dst) {
    int e = blockIdx.x * blockDim.x + threadIdx.x;
    if (e < N_SCAN_BLOCKS) g_bflag[e] = 0;
    if (e < N_EDGES) atomicAdd(&g_cnt[dst[e]], 1);
}

__global__ void __launch_bounds__(SCAN_BLK) k_scan(void) {
    __shared__ int s[2 * SCAN_BLK];
    __shared__ int s_exc;
    volatile int* flagv = g_bflag;
    volatile int* aggv  = g_bagg;
    volatile int* prev  = g_bpre;

    const int t   = threadIdx.x;
    const int bid = blockIdx.x;
    const int gi  = bid * SCAN_BLK + t;

    int v = (gi < N_NODES) ? g_cnt[gi] : 0;
    if (gi < N_NODES) g_dinv[gi] = rsqrtf((float)(v + 1));

    int* a = s; int* b = s + SCAN_BLK;
    a[t] = v;
    __syncthreads();
#pragma unroll
    for (int off = 1; off < SCAN_BLK; off <<= 1) {
        b[t] = a[t] + ((t >= off) ? a[t - off] : 0);
        int* tmp = a; a = b; b = tmp;
        __syncthreads();
    }
    const int lx = a[t] - v;
    const int S  = a[SCAN_BLK - 1];

    if (t == SCAN_BLK - 1) {
        if (bid == 0) { prev[0] = S; __threadfence(); flagv[0] = 2; }
        else          { aggv[bid] = S; __threadfence(); flagv[bid] = 1; }
    }
    __syncthreads();

    if (t < 32) {
        int exc = 0;
        int look = bid - 1;
        while (look >= 0) {
            int i = look - t;
            int f = 0, val = 0;
            if (i >= 0) {
                do { f = flagv[i]; } while (f == 0);
                __threadfence();
                val = (f == 2) ? prev[i] : aggv[i];
            }
            unsigned m2 = __ballot_sync(0xffffffffu, (i >= 0) && (f == 2));
            if (m2) {
                int stop = __ffs(m2) - 1;
                int c = (t <= stop) ? val : 0;
                exc += __reduce_add_sync(0xffffffffu, c);
                break;
            } else {
                int c = (i >= 0) ? val : 0;
                exc += __reduce_add_sync(0xffffffffu, c);
                look -= 32;
            }
        }
        if (t == 0) {
            if (bid != 0) { prev[bid] = exc + S; __threadfence(); flagv[bid] = 2; }
            s_exc = exc;
        }
    }
    __syncthreads();

    const int base = s_exc;
    if (gi < N_NODES) {
        int o = base + lx;
        g_offs[gi] = o;
        g_cursor[gi] = o;
    }
    if (bid == 0 && t == 0) g_offs[N_NODES] = N_EDGES;
}

__global__ void k_fill(const int* __restrict__ src, const int* __restrict__ dst) {
    int e = blockIdx.x * blockDim.x + threadIdx.x;
    if (e < N_NODES) g_cnt[e] = 0;
    if (e < N_EDGES) {
        int pos = atomicAdd(&g_cursor[dst[e]], 1);
        g_csr[pos] = src[e];
    }
}

// ---------------- GEMM1 (HMMA, proven R13) --------------------------------------

#define SA1_STRIDE 136
#define SB_STRIDE  72

__device__ __forceinline__ unsigned smem_u32(const void* p) {
    return (unsigned)__cvta_generic_to_shared(p);
}

__global__ void __launch_bounds__(128) k_gemm1(const float* __restrict__ x,
                                               const float* __restrict__ W1) {
    __shared__ __half sA[64 * SA1_STRIDE];
    __shared__ __half sB[128 * SB_STRIDE];
    const int tid  = threadIdx.x;
    const int wid  = tid >> 5;
    const int lane = tid & 31;
    const int nodeBase = blockIdx.x * 64;
    const int m0 = wid * 16;

#pragma unroll
    for (int i = tid; i < 2048; i += 128) {
        int k = i >> 4, f4 = i & 15;
        float4 v = ((const float4*)W1)[(size_t)k * 16 + f4];
        __half2* p = (__half2*)(sB + k * SB_STRIDE + f4 * 4);
        p[0] = __floats2half2_rn(v.x, v.y);
        p[1] = __floats2half2_rn(v.z, v.w);
    }
#pragma unroll
    for (int i = tid; i < 2048; i += 128) {
        int r = i >> 5, f4 = i & 31;
        float4 v = ((const float4*)x)[(size_t)(nodeBase + r) * 32 + f4];
        __half2* p = (__half2*)(sA + r * SA1_STRIDE + f4 * 4);
        p[0] = __floats2half2_rn(v.x, v.y);
        p[1] = __floats2half2_rn(v.z, v.w);
    }
    __syncthreads();

    float acc[8][4];
#pragma unroll
    for (int n = 0; n < 8; n++)
#pragma unroll
        for (int q = 0; q < 4; q++) acc[n][q] = 0.0f;

#pragma unroll
    for (int kk = 0; kk < 8; kk++) {
        int k0 = kk * 16;
        unsigned a0, a1, a2, a3;
        {
            unsigned addr = smem_u32(sA + (m0 + (lane & 15)) * SA1_STRIDE
                                        + k0 + (lane >> 4) * 8);
            asm volatile(
                "ldmatrix.sync.aligned.m8n8.x4.shared.b16 {%0,%1,%2,%3}, [%4];"
                : "=r"(a0), "=r"(a1), "=r"(a2), "=r"(a3) : "r"(addr));
        }
#pragma unroll
        for (int n = 0; n < 8; n++) {
            unsigned b0, b1;
            unsigned baddr = smem_u32(sB + (k0 + (lane & 15)) * SB_STRIDE + n * 8);
            asm volatile(
                "ldmatrix.sync.aligned.m8n8.x2.trans.shared.b16 {%0,%1}, [%2];"
                : "=r"(b0), "=r"(b1) : "r"(baddr));
            asm volatile(
                "mma.sync.aligned.m16n8k16.row.col.f32.f16.f16.f32 "
                "{%0,%1,%2,%3}, {%4,%5,%6,%7}, {%8,%9}, {%0,%1,%2,%3};"
                : "+f"(acc[n][0]), "+f"(acc[n][1]),
                  "+f"(acc[n][2]), "+f"(acc[n][3])
                : "r"(a0), "r"(a1), "r"(a2), "r"(a3), "r"(b0), "r"(b1));
        }
    }

    int r0 = nodeBase + m0 + (lane >> 2);
    int r1 = r0 + 8;
    float d0 = g_dinv[r0], d1 = g_dinv[r1];
    int cbase = (lane & 3);
#pragma unroll
    for (int n = 0; n < 8; n++) {
        ((__half2*)g_h1s)[(size_t)r0 * 32 + n * 4 + cbase] =
            __floats2half2_rn(d0 * acc[n][0], d0 * acc[n][1]);
        ((__half2*)g_h1s)[(size_t)r1 * 32 + n * 4 + cbase] =
            __floats2half2_rn(d1 * acc[n][2], d1 * acc[n][3]);
    }
}

// ---------------- FUSED agg1 + GEMM2 --------------------------------------------
// Block = 128 nodes, 256 thr / 8 warps.
// Phase A: warp w aggregates nodes [w*16, w*16+16) — lane-parallel 4-way gather
//          from g_h1s (proven R14 agg1), bias+relu, fp16 row -> sA (gemm layout).
// Phase B: proven K=64 HMMA gemm2 reading sA, epilogue dinv -> g_h2s.

#define SA_STRIDE 72
#define SB2_STRIDE 40

__global__ void __launch_bounds__(256) k_agg1gemm2(const float* __restrict__ b1,
                                                   const float* __restrict__ W2) {
    __shared__ __half sA[128 * SA_STRIDE];   // aggregated relu rows [node][k]
    __shared__ __half sB[64 * SB2_STRIDE];   // W2 [k][ch]
    const int tid  = threadIdx.x;
    const int wid  = tid >> 5;
    const int lane = tid & 31;
    const int nodeBase = blockIdx.x * 128;
    const int m0 = wid * 16;

    // W2 load (once)
#pragma unroll
    for (int i = tid; i < 512; i += 256) {
        int k = i >> 3, f4 = i & 7;
        float4 v = ((const float4*)W2)[i];
        __half2* p = (__half2*)(sB + k * SB2_STRIDE + f4 * 4);
        p[0] = __floats2half2_rn(v.x, v.y);
        p[1] = __floats2half2_rn(v.z, v.w);
    }

    // Phase A: aggregate 16 nodes per warp
    const int grp = lane >> 3;   // 0..3
    const int sub = lane & 7;    // 0..7
    const uint4* h4 = (const uint4*)g_h1s;   // 8 uint4 per 64-half row
    const float4* b4 = (const float4*)b1;

    for (int r = m0; r < m0 + 16; ++r) {
        int node = nodeBase + r;
        int beg = g_offs[node], end = g_offs[node + 1];

        float acc[8];
#pragma unroll
        for (int q = 0; q < 8; q++) acc[q] = 0.0f;

        for (int c = beg; c < end; c += 32) {
            int m = min(32, end - c);
            int idx = (c + lane < end) ? g_csr[c + lane] : 0;
            for (int t = 0; t < m; t += 4) {
                int slot = t + grp;
                int j = __shfl_sync(0xffffffffu, idx, slot & 31);
                if (slot < m) {
                    uint4 v = h4[(size_t)j * 8 + sub];
                    const __half2* hv = (const __half2*)&v;
#pragma unroll
                    for (int q = 0; q < 4; q++) {
                        float2 f = __half22float2(hv[q]);
                        acc[2 * q]     += f.x;
                        acc[2 * q + 1] += f.y;
                    }
                }
            }
        }
#pragma unroll
        for (int q = 0; q < 8; q++) {
            acc[q] += __shfl_xor_sync(0xffffffffu, acc[q], 8);
            acc[q] += __shfl_xor_sync(0xffffffffu, acc[q], 16);
        }
        if (lane < 8) {
            uint4 sv = h4[(size_t)node * 8 + lane];
            const __half2* shv = (const __half2*)&sv;
#pragma unroll
            for (int q = 0; q < 4; q++) {
                float2 f = __half22float2(shv[q]);
                acc[2 * q]     += f.x;
                acc[2 * q + 1] += f.y;
            }
            float di = g_dinv[node];
            float4 bA = b4[lane * 2], bB = b4[lane * 2 + 1];
            uint4 o;
            __half2* oh = (__half2*)&o;
            oh[0] = __floats2half2_rn(fmaxf(bA.x + di * acc[0], 0.0f),
                                      fmaxf(bA.y + di * acc[1], 0.0f));
            oh[1] = __floats2half2_rn(fmaxf(bA.z + di * acc[2], 0.0f),
                                      fmaxf(bA.w + di * acc[3], 0.0f));
            oh[2] = __floats2half2_rn(fmaxf(bB.x + di * acc[4], 0.0f),
                                      fmaxf(bB.y + di * acc[5], 0.0f));
            oh[3] = __floats2half2_rn(fmaxf(bB.z + di * acc[6], 0.0f),
                                      fmaxf(bB.w + di * acc[7], 0.0f));
            *(uint4*)(sA + r * SA_STRIDE + lane * 8) = o;
        }
    }
    __syncthreads();

    // Phase B: HMMA gemm2 (proven R11)
    float acc2[4][4];
#pragma unroll
    for (int n = 0; n < 4; n++)
#pragma unroll
        for (int q = 0; q < 4; q++) acc2[n][q] = 0.0f;

#pragma unroll
    for (int kk = 0; kk < 4; kk++) {
        int k0 = kk * 16;
        unsigned a0, a1, a2, a3;
        {
            unsigned addr = smem_u32(sA + (m0 + (lane & 15)) * SA_STRIDE
                                        + k0 + (lane >> 4) * 8);
            asm volatile(
                "ldmatrix.sync.aligned.m8n8.x4.shared.b16 {%0,%1,%2,%3}, [%4];"
                : "=r"(a0), "=r"(a1), "=r"(a2), "=r"(a3) : "r"(addr));
        }
#pragma unroll
        for (int n = 0; n < 4; n++) {
            unsigned b0, b1v;
            unsigned baddr = smem_u32(sB + (k0 + (lane & 15)) * SB2_STRIDE + n * 8);
            asm volatile(
                "ldmatrix.sync.aligned.m8n8.x2.trans.shared.b16 {%0,%1}, [%2];"
                : "=r"(b0), "=r"(b1v) : "r"(baddr));
            asm volatile(
                "mma.sync.aligned.m16n8k16.row.col.f32.f16.f16.f32 "
                "{%0,%1,%2,%3}, {%4,%5,%6,%7}, {%8,%9}, {%0,%1,%2,%3};"
                : "+f"(acc2[n][0]), "+f"(acc2[n][1]),
                  "+f"(acc2[n][2]), "+f"(acc2[n][3])
                : "r"(a0), "r"(a1), "r"(a2), "r"(a3), "r"(b0), "r"(b1v));
        }
    }

    int r0 = nodeBase + m0 + (lane >> 2);
    int r1 = r0 + 8;
    float d0 = g_dinv[r0], d1 = g_dinv[r1];
    int cbase = (lane & 3);
#pragma unroll
    for (int n = 0; n < 4; n++) {
        ((__half2*)g_h2s)[(size_t)r0 * 16 + n * 4 + cbase] =
            __floats2half2_rn(d0 * acc2[n][0], d0 * acc2[n][1]);
        ((__half2*)g_h2s)[(size_t)r1 * 16 + n * 4 + cbase] =
            __floats2half2_rn(d1 * acc2[n][2], d1 * acc2[n][3]);
    }
}

// ---------------- agg2: lane-parallel gather (8 neighbors / step, proven R14) --

__global__ void __launch_bounds__(256) k_agg2(const float* __restrict__ b2,
                                              float* __restrict__ out) {
    int node = blockIdx.x * 8 + (threadIdx.x >> 5);
    if (node >= N_NODES) return;
    const int lane = threadIdx.x & 31;
    const int grp  = lane >> 2;   // 0..7
    const int sub  = lane & 3;    // 0..3
    const uint4* h4 = (const uint4*)g_h2s;   // 4 uint4 per row
    int beg = g_offs[node], end = g_offs[node + 1];

    float acc[8];
#pragma unroll
    for (int q = 0; q < 8; q++) acc[q] = 0.0f;

    for (int c = beg; c < end; c += 32) {
        int m = min(32, end - c);
        int idx = (c + lane < end) ? g_csr[c + lane] : 0;
        for (int t = 0; t < m; t += 8) {
            int slot = t + grp;
            int j = __shfl_sync(0xffffffffu, idx, slot & 31);
            if (slot < m) {
                uint4 v = h4[(size_t)j * 4 + sub];
                const __half2* hv = (const __half2*)&v;
#pragma unroll
                for (int q = 0; q < 4; q++) {
                    float2 f = __half22float2(hv[q]);
                    acc[2 * q]     += f.x;
                    acc[2 * q + 1] += f.y;
                }
            }
        }
    }
#pragma unroll
    for (int q = 0; q < 8; q++) {
        acc[q] += __shfl_xor_sync(0xffffffffu, acc[q], 4);
        acc[q] += __shfl_xor_sync(0xffffffffu, acc[q], 8);
        acc[q] += __shfl_xor_sync(0xffffffffu, acc[q], 16);
    }
    if (lane < 4) {
        uint4 sv = h4[(size_t)node * 4 + lane];
        const __half2* shv = (const __half2*)&sv;
#pragma unroll
        for (int q = 0; q < 4; q++) {
            float2 f = __half22float2(shv[q]);
            acc[2 * q]     += f.x;
            acc[2 * q + 1] += f.y;
        }
        float di = g_dinv[node];
        const float4* b4 = (const float4*)b2;
        float4 bA = b4[lane * 2], bB = b4[lane * 2 + 1];
        float4 o0 = make_float4(bA.x + di * acc[0], bA.y + di * acc[1],
                                bA.z + di * acc[2], bA.w + di * acc[3]);
        float4 o1 = make_float4(bB.x + di * acc[4], bB.y + di * acc[5],
                                bB.z + di * acc[6], bB.w + di * acc[7]);
        ((float4*)out)[(size_t)node * 8 + lane * 2]     = o0;
        ((float4*)out)[(size_t)node * 8 + lane * 2 + 1] = o1;
    }
}

// ---------------- launch (single stream, 6 kernels) ----------------

extern "C" void kernel_launch(void* const* d_in, const int* in_sizes, int n_in,
                              void* d_out, int out_size) {
    const float* x   = (const float*)d_in[0];
    const int*   ei  = (const int*)d_in[1];
    const float* W1  = (const float*)d_in[2];
    const float* b1  = (const float*)d_in[3];
    const float* W2  = (const float*)d_in[4];
    const float* b2  = (const float*)d_in[5];
    float*       out = (float*)d_out;

    const int* src = ei;
    const int* dst = ei + N_EDGES;

    k_cnt      <<<(N_EDGES + 255) / 256, 256>>>(dst);
    k_scan     <<<N_SCAN_BLOCKS, SCAN_BLK>>>();
    k_fill     <<<(N_EDGES + 255) / 256, 256>>>(src, dst);

    k_gemm1    <<<N_NODES / 64, 128>>>(x, W1);
    k_agg1gemm2<<<N_NODES / 128, 256>>>(b1, W2);
    k_agg2     <<<(N_NODES + 7) / 8, 256>>>(b2, out);
}

// round 16
// speedup vs baseline: 1.1037x; 1.1037x over previous
#include <cuda_runtime.h>
#include <cuda_fp16.h>

#define N_NODES 80000
#define N_EDGES 1280000
#define IN_CH 128
#define HID 64
#define OUT_CH 32

#define SCAN_BLK 512
#define N_SCAN_BLOCKS ((N_NODES + SCAN_BLK - 1) / SCAN_BLK)   // 157

#define GEMM1_BLOCKS (N_NODES / 64)      // 1250
#define FILL_BLOCKS  (N_EDGES / 128)     // 10000

__device__ __align__(256) float  g_dinv[N_NODES];
__device__ __align__(256) int    g_cnt [N_NODES];
__device__ __align__(256) int    g_offs[N_NODES + 1];
__device__ __align__(256) int    g_cursor[N_NODES];
__device__ __align__(256) int    g_csr [N_EDGES];
__device__ __align__(256) int    g_bagg [N_SCAN_BLOCKS];
__device__ __align__(256) int    g_bpre [N_SCAN_BLOCKS];
__device__ __align__(256) int    g_bflag[N_SCAN_BLOCKS];
__device__ __align__(256) __half g_h1s [(size_t)N_NODES * HID];     // fp16: dinv*(x@W1)
__device__ __align__(256) __half g_out1[(size_t)N_NODES * HID];     // fp16: relu(b1+..)
__device__ __align__(256) __half g_h2s [(size_t)N_NODES * OUT_CH];  // fp16: dinv*(out1@W2)

// ---------------- CSR build (proven R12) ----------------

__global__ void k_cnt(const int* __restrict__ dst) {
    int e = blockIdx.x * blockDim.x + threadIdx.x;
    if (e < N_SCAN_BLOCKS) g_bflag[e] = 0;
    if (e < N_EDGES) atomicAdd(&g_cnt[dst[e]], 1);
}

__global__ void __launch_bounds__(SCAN_BLK) k_scan(void) {
    __shared__ int s[2 * SCAN_BLK];
    __shared__ int s_exc;
    volatile int* flagv = g_bflag;
    volatile int* aggv  = g_bagg;
    volatile int* prev  = g_bpre;

    const int t   = threadIdx.x;
    const int bid = blockIdx.x;
    const int gi  = bid * SCAN_BLK + t;

    int v = (gi < N_NODES) ? g_cnt[gi] : 0;
    if (gi < N_NODES) g_dinv[gi] = rsqrtf((float)(v + 1));

    int* a = s; int* b = s + SCAN_BLK;
    a[t] = v;
    __syncthreads();
#pragma unroll
    for (int off = 1; off < SCAN_BLK; off <<= 1) {
        b[t] = a[t] + ((t >= off) ? a[t - off] : 0);
        int* tmp = a; a = b; b = tmp;
        __syncthreads();
    }
    const int lx = a[t] - v;
    const int S  = a[SCAN_BLK - 1];

    if (t == SCAN_BLK - 1) {
        if (bid == 0) { prev[0] = S; __threadfence(); flagv[0] = 2; }
        else          { aggv[bid] = S; __threadfence(); flagv[bid] = 1; }
    }
    __syncthreads();

    if (t < 32) {
        int exc = 0;
        int look = bid - 1;
        while (look >= 0) {
            int i = look - t;
            int f = 0, val = 0;
            if (i >= 0) {
                do { f = flagv[i]; } while (f == 0);
                __threadfence();
                val = (f == 2) ? prev[i] : aggv[i];
            }
            unsigned m2 = __ballot_sync(0xffffffffu, (i >= 0) && (f == 2));
            if (m2) {
                int stop = __ffs(m2) - 1;
                int c = (t <= stop) ? val : 0;
                exc += __reduce_add_sync(0xffffffffu, c);
                break;
            } else {
                int c = (i >= 0) ? val : 0;
                exc += __reduce_add_sync(0xffffffffu, c);
                look -= 32;
            }
        }
        if (t == 0) {
            if (bid != 0) { prev[bid] = exc + S; __threadfence(); flagv[bid] = 2; }
            s_exc = exc;
        }
    }
    __syncthreads();

    const int base = s_exc;
    if (gi < N_NODES) {
        int o = base + lx;
        g_offs[gi] = o;
        g_cursor[gi] = o;
    }
    if (bid == 0 && t == 0) g_offs[N_NODES] = N_EDGES;
}

// ---------------- MERGED fill + GEMM1 -------------------------------------------
// Blocks [0, GEMM1_BLOCKS): HMMA gemm1 (proven R13, 64 nodes, 128 thr).
// Blocks [GEMM1_BLOCKS, +FILL_BLOCKS): CSR fill (atomic cursor) + g_cnt re-zero.
// Independent work, disjoint state, both depend only on k_scan.

#define SA1_STRIDE 136
#define SB_STRIDE  72

__device__ __forceinline__ unsigned smem_u32(const void* p) {
    return (unsigned)__cvta_generic_to_shared(p);
}

__global__ void __launch_bounds__(128) k_fill_gemm1(const float* __restrict__ x,
                                                    const float* __restrict__ W1,
                                                    const int* __restrict__ src,
                                                    const int* __restrict__ dst) {
    __shared__ __half sA[64 * SA1_STRIDE];
    __shared__ __half sB[128 * SB_STRIDE];

    if (blockIdx.x >= GEMM1_BLOCKS) {
        // ---- fill branch ----
        int e = (blockIdx.x - GEMM1_BLOCKS) * 128 + threadIdx.x;
        if (e < N_NODES) g_cnt[e] = 0;   // restore zero-invariant for next replay
        if (e < N_EDGES) {
            int pos = atomicAdd(&g_cursor[dst[e]], 1);
            g_csr[pos] = src[e];
        }
        return;
    }

    // ---- gemm1 branch (proven R13) ----
    const int tid  = threadIdx.x;
    const int wid  = tid >> 5;
    const int lane = tid & 31;
    const int nodeBase = blockIdx.x * 64;
    const int m0 = wid * 16;

#pragma unroll
    for (int i = tid; i < 2048; i += 128) {
        int k = i >> 4, f4 = i & 15;
        float4 v = ((const float4*)W1)[(size_t)k * 16 + f4];
        __half2* p = (__half2*)(sB + k * SB_STRIDE + f4 * 4);
        p[0] = __floats2half2_rn(v.x, v.y);
        p[1] = __floats2half2_rn(v.z, v.w);
    }
#pragma unroll
    for (int i = tid; i < 2048; i += 128) {
        int r = i >> 5, f4 = i & 31;
        float4 v = ((const float4*)x)[(size_t)(nodeBase + r) * 32 + f4];
        __half2* p = (__half2*)(sA + r * SA1_STRIDE + f4 * 4);
        p[0] = __floats2half2_rn(v.x, v.y);
        p[1] = __floats2half2_rn(v.z, v.w);
    }
    __syncthreads();

    float acc[8][4];
#pragma unroll
    for (int n = 0; n < 8; n++)
#pragma unroll
        for (int q = 0; q < 4; q++) acc[n][q] = 0.0f;

#pragma unroll
    for (int kk = 0; kk < 8; kk++) {
        int k0 = kk * 16;
        unsigned a0, a1, a2, a3;
        {
            unsigned addr = smem_u32(sA + (m0 + (lane & 15)) * SA1_STRIDE
                                        + k0 + (lane >> 4) * 8);
            asm volatile(
                "ldmatrix.sync.aligned.m8n8.x4.shared.b16 {%0,%1,%2,%3}, [%4];"
                : "=r"(a0), "=r"(a1), "=r"(a2), "=r"(a3) : "r"(addr));
        }
#pragma unroll
        for (int n = 0; n < 8; n++) {
            unsigned b0, b1;
            unsigned baddr = smem_u32(sB + (k0 + (lane & 15)) * SB_STRIDE + n * 8);
            asm volatile(
                "ldmatrix.sync.aligned.m8n8.x2.trans.shared.b16 {%0,%1}, [%2];"
                : "=r"(b0), "=r"(b1) : "r"(baddr));
            asm volatile(
                "mma.sync.aligned.m16n8k16.row.col.f32.f16.f16.f32 "
                "{%0,%1,%2,%3}, {%4,%5,%6,%7}, {%8,%9}, {%0,%1,%2,%3};"
                : "+f"(acc[n][0]), "+f"(acc[n][1]),
                  "+f"(acc[n][2]), "+f"(acc[n][3])
                : "r"(a0), "r"(a1), "r"(a2), "r"(a3), "r"(b0), "r"(b1));
        }
    }

    int r0 = nodeBase + m0 + (lane >> 2);
    int r1 = r0 + 8;
    float d0 = g_dinv[r0], d1 = g_dinv[r1];
    int cbase = (lane & 3);
#pragma unroll
    for (int n = 0; n < 8; n++) {
        ((__half2*)g_h1s)[(size_t)r0 * 32 + n * 4 + cbase] =
            __floats2half2_rn(d0 * acc[n][0], d0 * acc[n][1]);
        ((__half2*)g_h1s)[(size_t)r1 * 32 + n * 4 + cbase] =
            __floats2half2_rn(d1 * acc[n][2], d1 * acc[n][3]);
    }
}

// ---------------- agg1: lane-parallel gather (4 neighbors / step, proven R14) --

__global__ void __launch_bounds__(256) k_agg1(const float* __restrict__ b1) {
    int node = blockIdx.x * 8 + (threadIdx.x >> 5);
    if (node >= N_NODES) return;
    const int lane = threadIdx.x & 31;
    const int grp  = lane >> 3;   // 0..3
    const int sub  = lane & 7;    // 0..7
    const uint4* h4 = (const uint4*)g_h1s;   // 8 uint4 per row
    int beg = g_offs[node], end = g_offs[node + 1];

    float acc[8];
#pragma unroll
    for (int q = 0; q < 8; q++) acc[q] = 0.0f;

    for (int c = beg; c < end; c += 32) {
        int m = min(32, end - c);
        int idx = (c + lane < end) ? g_csr[c + lane] : 0;
        for (int t = 0; t < m; t += 4) {
            int slot = t + grp;
            int j = __shfl_sync(0xffffffffu, idx, slot & 31);
            if (slot < m) {
                uint4 v = h4[(size_t)j * 8 + sub];
                const __half2* hv = (const __half2*)&v;
#pragma unroll
                for (int q = 0; q < 4; q++) {
                    float2 f = __half22float2(hv[q]);
                    acc[2 * q]     += f.x;
                    acc[2 * q + 1] += f.y;
                }
            }
        }
    }
#pragma unroll
    for (int q = 0; q < 8; q++) {
        acc[q] += __shfl_xor_sync(0xffffffffu, acc[q], 8);
        acc[q] += __shfl_xor_sync(0xffffffffu, acc[q], 16);
    }
    if (lane < 8) {
        uint4 sv = h4[(size_t)node * 8 + lane];
        const __half2* shv = (const __half2*)&sv;
#pragma unroll
        for (int q = 0; q < 4; q++) {
            float2 f = __half22float2(shv[q]);
            acc[2 * q]     += f.x;
            acc[2 * q + 1] += f.y;
        }
        float di = g_dinv[node];
        const float4* b4 = (const float4*)b1;
        float4 bA = b4[lane * 2], bB = b4[lane * 2 + 1];
        uint4 o;
        __half2* oh = (__half2*)&o;
        oh[0] = __floats2half2_rn(fmaxf(bA.x + di * acc[0], 0.0f),
                                  fmaxf(bA.y + di * acc[1], 0.0f));
        oh[1] = __floats2half2_rn(fmaxf(bA.z + di * acc[2], 0.0f),
                                  fmaxf(bA.w + di * acc[3], 0.0f));
        oh[2] = __floats2half2_rn(fmaxf(bB.x + di * acc[4], 0.0f),
                                  fmaxf(bB.y + di * acc[5], 0.0f));
        oh[3] = __floats2half2_rn(fmaxf(bB.z + di * acc[6], 0.0f),
                                  fmaxf(bB.w + di * acc[7], 0.0f));
        ((uint4*)g_out1)[(size_t)node * 8 + lane] = o;
    }
}

// ---------------- GEMM2 (HMMA, K=64, proven R11) --------------------------------

#define SA_STRIDE 72
#define SB2_STRIDE 40

__global__ void __launch_bounds__(256) k_gemm2(const float* __restrict__ W2) {
    __shared__ __half sA[128 * SA_STRIDE];
    __shared__ __half sB[64 * SB2_STRIDE];
    const int tid  = threadIdx.x;
    const int wid  = tid >> 5;
    const int lane = tid & 31;
    const int nodeBase = blockIdx.x * 128;
    const int m0 = wid * 16;

#pragma unroll
    for (int i = tid; i < 512; i += 256) {
        int k = i >> 3, f4 = i & 7;
        float4 v = ((const float4*)W2)[i];
        __half2* p = (__half2*)(sB + k * SB2_STRIDE + f4 * 4);
        p[0] = __floats2half2_rn(v.x, v.y);
        p[1] = __floats2half2_rn(v.z, v.w);
    }
#pragma unroll
    for (int i = tid; i < 1024; i += 256) {
        int r = i >> 3, q = i & 7;
        uint4 v = ((const uint4*)g_out1)[(size_t)(nodeBase + r) * 8 + q];
        *(uint4*)(sA + r * SA_STRIDE + q * 8) = v;
    }
    __syncthreads();

    float acc[4][4];
#pragma unroll
    for (int n = 0; n < 4; n++)
#pragma unroll
        for (int q = 0; q < 4; q++) acc[n][q] = 0.0f;

#pragma unroll
    for (int kk = 0; kk < 4; kk++) {
        int k0 = kk * 16;
        unsigned a0, a1, a2, a3;
        {
            unsigned addr = smem_u32(sA + (m0 + (lane & 15)) * SA_STRIDE
                                        + k0 + (lane >> 4) * 8);
            asm volatile(
                "ldmatrix.sync.aligned.m8n8.x4.shared.b16 {%0,%1,%2,%3}, [%4];"
                : "=r"(a0), "=r"(a1), "=r"(a2), "=r"(a3) : "r"(addr));
        }
#pragma unroll
        for (int n = 0; n < 4; n++) {
            unsigned b0, b1;
            unsigned baddr = smem_u32(sB + (k0 + (lane & 15)) * SB2_STRIDE + n * 8);
            asm volatile(
                "ldmatrix.sync.aligned.m8n8.x2.trans.shared.b16 {%0,%1}, [%2];"
                : "=r"(b0), "=r"(b1) : "r"(baddr));
            asm volatile(
                "mma.sync.aligned.m16n8k16.row.col.f32.f16.f16.f32 "
                "{%0,%1,%2,%3}, {%4,%5,%6,%7}, {%8,%9}, {%0,%1,%2,%3};"
                : "+f"(acc[n][0]), "+f"(acc[n][1]),
                  "+f"(acc[n][2]), "+f"(acc[n][3])
                : "r"(a0), "r"(a1), "r"(a2), "r"(a3), "r"(b0), "r"(b1));
        }
    }

    int r0 = nodeBase + m0 + (lane >> 2);
    int r1 = r0 + 8;
    float d0 = g_dinv[r0], d1 = g_dinv[r1];
    int cbase = (lane & 3);
#pragma unroll
    for (int n = 0; n < 4; n++) {
        ((__half2*)g_h2s)[(size_t)r0 * 16 + n * 4 + cbase] =
            __floats2half2_rn(d0 * acc[n][0], d0 * acc[n][1]);
        ((__half2*)g_h2s)[(size_t)r1 * 16 + n * 4 + cbase] =
            __floats2half2_rn(d1 * acc[n][2], d1 * acc[n][3]);
    }
}

// ---------------- agg2: lane-parallel gather (8 neighbors / step, proven R14) --

__global__ void __launch_bounds__(256) k_agg2(const float* __restrict__ b2,
                                              float* __restrict__ out) {
    int node = blockIdx.x * 8 + (threadIdx.x >> 5);
    if (node >= N_NODES) return;
    const int lane = threadIdx.x & 31;
    const int grp  = lane >> 2;   // 0..7
    const int sub  = lane & 3;    // 0..3
    const uint4* h4 = (const uint4*)g_h2s;   // 4 uint4 per row
    int beg = g_offs[node], end = g_offs[node + 1];

    float acc[8];
#pragma unroll
    for (int q = 0; q < 8; q++) acc[q] = 0.0f;

    for (int c = beg; c < end; c += 32) {
        int m = min(32, end - c);
        int idx = (c + lane < end) ? g_csr[c + lane] : 0;
        for (int t = 0; t < m; t += 8) {
            int slot = t + grp;
            int j = __shfl_sync(0xffffffffu, idx, slot & 31);
            if (slot < m) {
                uint4 v = h4[(size_t)j * 4 + sub];
                const __half2* hv = (const __half2*)&v;
#pragma unroll
                for (int q = 0; q < 4; q++) {
                    float2 f = __half22float2(hv[q]);
                    acc[2 * q]     += f.x;
                    acc[2 * q + 1] += f.y;
                }
            }
        }
    }
#pragma unroll
    for (int q = 0; q < 8; q++) {
        acc[q] += __shfl_xor_sync(0xffffffffu, acc[q], 4);
        acc[q] += __shfl_xor_sync(0xffffffffu, acc[q], 8);
        acc[q] += __shfl_xor_sync(0xffffffffu, acc[q], 16);
    }
    if (lane < 4) {
        uint4 sv = h4[(size_t)node * 4 + lane];
        const __half2* shv = (const __half2*)&sv;
#pragma unroll
        for (int q = 0; q < 4; q++) {
            float2 f = __half22float2(shv[q]);
            acc[2 * q]     += f.x;
            acc[2 * q + 1] += f.y;
        }
        float di = g_dinv[node];
        const float4* b4 = (const float4*)b2;
        float4 bA = b4[lane * 2], bB = b4[lane * 2 + 1];
        float4 o0 = make_float4(bA.x + di * acc[0], bA.y + di * acc[1],
                                bA.z + di * acc[2], bA.w + di * acc[3]);
        float4 o1 = make_float4(bB.x + di * acc[4], bB.y + di * acc[5],
                                bB.z + di * acc[6], bB.w + di * acc[7]);
        ((float4*)out)[(size_t)node * 8 + lane * 2]     = o0;
        ((float4*)out)[(size_t)node * 8 + lane * 2 + 1] = o1;
    }
}

// ---------------- launch (single stream, 6 kernels) ----------------

extern "C" void kernel_launch(void* const* d_in, const int* in_sizes, int n_in,
                              void* d_out, int out_size) {
    const float* x   = (const float*)d_in[0];
    const int*   ei  = (const int*)d_in[1];
    const float* W1  = (const float*)d_in[2];
    const float* b1  = (const float*)d_in[3];
    const float* W2  = (const float*)d_in[4];
    const float* b2  = (const float*)d_in[5];
    float*       out = (float*)d_out;

    const int* src = ei;
    const int* dst = ei + N_EDGES;

    k_cnt       <<<(N_EDGES + 255) / 256, 256>>>(dst);
    k_scan      <<<N_SCAN_BLOCKS, SCAN_BLK>>>();
    k_fill_gemm1<<<GEMM1_BLOCKS + FILL_BLOCKS, 128>>>(x, W1, src, dst);
    k_agg1      <<<(N_NODES + 7) / 8, 256>>>(b1);
    k_gemm2     <<<N_NODES / 128, 256>>>(W2);
    k_agg2      <<<(N_NODES + 7) / 8, 256>>>(b2, out);
}

// round 17
// speedup vs baseline: 1.1567x; 1.0480x over previous
#include <cuda_runtime.h>
#include <cuda_fp16.h>

#define N_NODES 80000
#define N_EDGES 1280000
#define IN_CH 128
#define HID 64
#define OUT_CH 32

#define SCAN_BLK 512
#define N_SCAN_BLOCKS ((N_NODES + SCAN_BLK - 1) / SCAN_BLK)   // 157

#define GEMM1_BLOCKS (N_NODES / 64)      // 1250
#define FILL_BLOCKS  (N_EDGES / 128)     // 10000

__device__ __align__(256) float  g_dinv[N_NODES];
__device__ __align__(256) int    g_cnt [N_NODES];
__device__ __align__(256) int    g_offs[N_NODES + 1];
__device__ __align__(256) int    g_cursor[N_NODES];
__device__ __align__(256) int    g_csr [N_EDGES];
__device__ __align__(256) int    g_bagg [N_SCAN_BLOCKS];
__device__ __align__(256) int    g_bpre [N_SCAN_BLOCKS];
__device__ __align__(256) int    g_bflag[N_SCAN_BLOCKS];
__device__ __align__(256) __half g_h1s [(size_t)N_NODES * HID];     // fp16: dinv*(x@W1)
__device__ __align__(256) __half g_out1[(size_t)N_NODES * HID];     // fp16: relu(b1+..)
__device__ __align__(256) __half g_h2s [(size_t)N_NODES * OUT_CH];  // fp16: dinv*(out1@W2)

// ---------------- CSR build (proven R12) ----------------

__global__ void k_cnt(const int* __restrict__ dst) {
    int e = blockIdx.x * blockDim.x + threadIdx.x;
    if (e < N_SCAN_BLOCKS) g_bflag[e] = 0;
    if (e < N_EDGES) atomicAdd(&g_cnt[dst[e]], 1);
}

__global__ void __launch_bounds__(SCAN_BLK) k_scan(void) {
    __shared__ int s[2 * SCAN_BLK];
    __shared__ int s_exc;
    volatile int* flagv = g_bflag;
    volatile int* aggv  = g_bagg;
    volatile int* prev  = g_bpre;

    const int t   = threadIdx.x;
    const int bid = blockIdx.x;
    const int gi  = bid * SCAN_BLK + t;

    int v = (gi < N_NODES) ? g_cnt[gi] : 0;
    if (gi < N_NODES) g_dinv[gi] = rsqrtf((float)(v + 1));

    int* a = s; int* b = s + SCAN_BLK;
    a[t] = v;
    __syncthreads();
#pragma unroll
    for (int off = 1; off < SCAN_BLK; off <<= 1) {
        b[t] = a[t] + ((t >= off) ? a[t - off] : 0);
        int* tmp = a; a = b; b = tmp;
        __syncthreads();
    }
    const int lx = a[t] - v;
    const int S  = a[SCAN_BLK - 1];

    if (t == SCAN_BLK - 1) {
        if (bid == 0) { prev[0] = S; __threadfence(); flagv[0] = 2; }
        else          { aggv[bid] = S; __threadfence(); flagv[bid] = 1; }
    }
    __syncthreads();

    if (t < 32) {
        int exc = 0;
        int look = bid - 1;
        while (look >= 0) {
            int i = look - t;
            int f = 0, val = 0;
            if (i >= 0) {
                do { f = flagv[i]; } while (f == 0);
                __threadfence();
                val = (f == 2) ? prev[i] : aggv[i];
            }
            unsigned m2 = __ballot_sync(0xffffffffu, (i >= 0) && (f == 2));
            if (m2) {
                int stop = __ffs(m2) - 1;
                int c = (t <= stop) ? val : 0;
                exc += __reduce_add_sync(0xffffffffu, c);
                break;
            } else {
                int c = (i >= 0) ? val : 0;
                exc += __reduce_add_sync(0xffffffffu, c);
                look -= 32;
            }
        }
        if (t == 0) {
            if (bid != 0) { prev[bid] = exc + S; __threadfence(); flagv[bid] = 2; }
            s_exc = exc;
        }
    }
    __syncthreads();

    const int base = s_exc;
    if (gi < N_NODES) {
        int o = base + lx;
        g_offs[gi] = o;
        g_cursor[gi] = o;
    }
    if (bid == 0 && t == 0) g_offs[N_NODES] = N_EDGES;
}

// ---------------- MERGED fill + GEMM1 (proven R16) -------------------------------

#define SA1_STRIDE 136
#define SB_STRIDE  72

__device__ __forceinline__ unsigned smem_u32(const void* p) {
    return (unsigned)__cvta_generic_to_shared(p);
}

__global__ void __launch_bounds__(128) k_fill_gemm1(const float* __restrict__ x,
                                                    const float* __restrict__ W1,
                                                    const int* __restrict__ src,
                                                    const int* __restrict__ dst) {
    __shared__ __half sA[64 * SA1_STRIDE];
    __shared__ __half sB[128 * SB_STRIDE];

    if (blockIdx.x >= GEMM1_BLOCKS) {
        int e = (blockIdx.x - GEMM1_BLOCKS) * 128 + threadIdx.x;
        if (e < N_NODES) g_cnt[e] = 0;
        if (e < N_EDGES) {
            int pos = atomicAdd(&g_cursor[dst[e]], 1);
            g_csr[pos] = src[e];
        }
        return;
    }

    const int tid  = threadIdx.x;
    const int wid  = tid >> 5;
    const int lane = tid & 31;
    const int nodeBase = blockIdx.x * 64;
    const int m0 = wid * 16;

#pragma unroll
    for (int i = tid; i < 2048; i += 128) {
        int k = i >> 4, f4 = i & 15;
        float4 v = ((const float4*)W1)[(size_t)k * 16 + f4];
        __half2* p = (__half2*)(sB + k * SB_STRIDE + f4 * 4);
        p[0] = __floats2half2_rn(v.x, v.y);
        p[1] = __floats2half2_rn(v.z, v.w);
    }
#pragma unroll
    for (int i = tid; i < 2048; i += 128) {
        int r = i >> 5, f4 = i & 31;
        float4 v = ((const float4*)x)[(size_t)(nodeBase + r) * 32 + f4];
        __half2* p = (__half2*)(sA + r * SA1_STRIDE + f4 * 4);
        p[0] = __floats2half2_rn(v.x, v.y);
        p[1] = __floats2half2_rn(v.z, v.w);
    }
    __syncthreads();

    float acc[8][4];
#pragma unroll
    for (int n = 0; n < 8; n++)
#pragma unroll
        for (int q = 0; q < 4; q++) acc[n][q] = 0.0f;

#pragma unroll
    for (int kk = 0; kk < 8; kk++) {
        int k0 = kk * 16;
        unsigned a0, a1, a2, a3;
        {
            unsigned addr = smem_u32(sA + (m0 + (lane & 15)) * SA1_STRIDE
                                        + k0 + (lane >> 4) * 8);
            asm volatile(
                "ldmatrix.sync.aligned.m8n8.x4.shared.b16 {%0,%1,%2,%3}, [%4];"
                : "=r"(a0), "=r"(a1), "=r"(a2), "=r"(a3) : "r"(addr));
        }
#pragma unroll
        for (int n = 0; n < 8; n++) {
            unsigned b0, b1;
            unsigned baddr = smem_u32(sB + (k0 + (lane & 15)) * SB_STRIDE + n * 8);
            asm volatile(
                "ldmatrix.sync.aligned.m8n8.x2.trans.shared.b16 {%0,%1}, [%2];"
                : "=r"(b0), "=r"(b1) : "r"(baddr));
            asm volatile(
                "mma.sync.aligned.m16n8k16.row.col.f32.f16.f16.f32 "
                "{%0,%1,%2,%3}, {%4,%5,%6,%7}, {%8,%9}, {%0,%1,%2,%3};"
                : "+f"(acc[n][0]), "+f"(acc[n][1]),
                  "+f"(acc[n][2]), "+f"(acc[n][3])
                : "r"(a0), "r"(a1), "r"(a2), "r"(a3), "r"(b0), "r"(b1));
        }
    }

    int r0 = nodeBase + m0 + (lane >> 2);
    int r1 = r0 + 8;
    float d0 = g_dinv[r0], d1 = g_dinv[r1];
    int cbase = (lane & 3);
#pragma unroll
    for (int n = 0; n < 8; n++) {
        ((__half2*)g_h1s)[(size_t)r0 * 32 + n * 4 + cbase] =
            __floats2half2_rn(d0 * acc[n][0], d0 * acc[n][1]);
        ((__half2*)g_h1s)[(size_t)r1 * 32 + n * 4 + cbase] =
            __floats2half2_rn(d1 * acc[n][2], d1 * acc[n][3]);
    }
}

// ---------------- agg1: paired gather, fp16 pre-add (8 neighbors / iter) -------
// Warp = node, 4 groups x 8 lanes. Per iteration each group handles neighbors
// slot t+grp and t+4+grp: 2 LDG, 4 HADD2, then ONE convert+fp32-add of the sum.

__global__ void __launch_bounds__(256) k_agg1(const float* __restrict__ b1) {
    int node = blockIdx.x * 8 + (threadIdx.x >> 5);
    if (node >= N_NODES) return;
    const int lane = threadIdx.x & 31;
    const int grp  = lane >> 3;   // 0..3
    const int sub  = lane & 7;    // 0..7
    const uint4* h4 = (const uint4*)g_h1s;   // 8 uint4 per row
    int beg = g_offs[node], end = g_offs[node + 1];

    float acc[8];
#pragma unroll
    for (int q = 0; q < 8; q++) acc[q] = 0.0f;
    const uint4 zero4 = make_uint4(0u, 0u, 0u, 0u);

    for (int c = beg; c < end; c += 32) {
        int m = min(32, end - c);
        int idx = (c + lane < end) ? g_csr[c + lane] : 0;
        for (int t = 0; t < m; t += 8) {
            int s0 = t + grp;
            int s1 = t + 4 + grp;
            int j0 = __shfl_sync(0xffffffffu, idx, s0 & 31);
            int j1 = __shfl_sync(0xffffffffu, idx, s1 & 31);
            uint4 v0 = (s0 < m) ? h4[(size_t)j0 * 8 + sub] : zero4;
            uint4 v1 = (s1 < m) ? h4[(size_t)j1 * 8 + sub] : zero4;
            const __half2* a = (const __half2*)&v0;
            const __half2* b = (const __half2*)&v1;
#pragma unroll
            for (int q = 0; q < 4; q++) {
                float2 f = __half22float2(__hadd2(a[q], b[q]));
                acc[2 * q]     += f.x;
                acc[2 * q + 1] += f.y;
            }
        }
    }
#pragma unroll
    for (int q = 0; q < 8; q++) {
        acc[q] += __shfl_xor_sync(0xffffffffu, acc[q], 8);
        acc[q] += __shfl_xor_sync(0xffffffffu, acc[q], 16);
    }
    if (lane < 8) {
        uint4 sv = h4[(size_t)node * 8 + lane];
        const __half2* shv = (const __half2*)&sv;
#pragma unroll
        for (int q = 0; q < 4; q++) {
            float2 f = __half22float2(shv[q]);
            acc[2 * q]     += f.x;
            acc[2 * q + 1] += f.y;
        }
        float di = g_dinv[node];
        const float4* b4 = (const float4*)b1;
        float4 bA = b4[lane * 2], bB = b4[lane * 2 + 1];
        uint4 o;
        __half2* oh = (__half2*)&o;
        oh[0] = __floats2half2_rn(fmaxf(bA.x + di * acc[0], 0.0f),
                                  fmaxf(bA.y + di * acc[1], 0.0f));
        oh[1] = __floats2half2_rn(fmaxf(bA.z + di * acc[2], 0.0f),
                                  fmaxf(bA.w + di * acc[3], 0.0f));
        oh[2] = __floats2half2_rn(fmaxf(bB.x + di * acc[4], 0.0f),
                                  fmaxf(bB.y + di * acc[5], 0.0f));
        oh[3] = __floats2half2_rn(fmaxf(bB.z + di * acc[6], 0.0f),
                                  fmaxf(bB.w + di * acc[7], 0.0f));
        ((uint4*)g_out1)[(size_t)node * 8 + lane] = o;
    }
}

// ---------------- GEMM2 (HMMA, K=64, proven R11) --------------------------------

#define SA_STRIDE 72
#define SB2_STRIDE 40

__global__ void __launch_bounds__(256) k_gemm2(const float* __restrict__ W2) {
    __shared__ __half sA[128 * SA_STRIDE];
    __shared__ __half sB[64 * SB2_STRIDE];
    const int tid  = threadIdx.x;
    const int wid  = tid >> 5;
    const int lane = tid & 31;
    const int nodeBase = blockIdx.x * 128;
    const int m0 = wid * 16;

#pragma unroll
    for (int i = tid; i < 512; i += 256) {
        int k = i >> 3, f4 = i & 7;
        float4 v = ((const float4*)W2)[i];
        __half2* p = (__half2*)(sB + k * SB2_STRIDE + f4 * 4);
        p[0] = __floats2half2_rn(v.x, v.y);
        p[1] = __floats2half2_rn(v.z, v.w);
    }
#pragma unroll
    for (int i = tid; i < 1024; i += 256) {
        int r = i >> 3, q = i & 7;
        uint4 v = ((const uint4*)g_out1)[(size_t)(nodeBase + r) * 8 + q];
        *(uint4*)(sA + r * SA_STRIDE + q * 8) = v;
    }
    __syncthreads();

    float acc[4][4];
#pragma unroll
    for (int n = 0; n < 4; n++)
#pragma unroll
        for (int q = 0; q < 4; q++) acc[n][q] = 0.0f;

#pragma unroll
    for (int kk = 0; kk < 4; kk++) {
        int k0 = kk * 16;
        unsigned a0, a1, a2, a3;
        {
            unsigned addr = smem_u32(sA + (m0 + (lane & 15)) * SA_STRIDE
                                        + k0 + (lane >> 4) * 8);
            asm volatile(
                "ldmatrix.sync.aligned.m8n8.x4.shared.b16 {%0,%1,%2,%3}, [%4];"
                : "=r"(a0), "=r"(a1), "=r"(a2), "=r"(a3) : "r"(addr));
        }
#pragma unroll
        for (int n = 0; n < 4; n++) {
            unsigned b0, b1;
            unsigned baddr = smem_u32(sB + (k0 + (lane & 15)) * SB2_STRIDE + n * 8);
            asm volatile(
                "ldmatrix.sync.aligned.m8n8.x2.trans.shared.b16 {%0,%1}, [%2];"
                : "=r"(b0), "=r"(b1) : "r"(baddr));
            asm volatile(
                "mma.sync.aligned.m16n8k16.row.col.f32.f16.f16.f32 "
                "{%0,%1,%2,%3}, {%4,%5,%6,%7}, {%8,%9}, {%0,%1,%2,%3};"
                : "+f"(acc[n][0]), "+f"(acc[n][1]),
                  "+f"(acc[n][2]), "+f"(acc[n][3])
                : "r"(a0), "r"(a1), "r"(a2), "r"(a3), "r"(b0), "r"(b1));
        }
    }

    int r0 = nodeBase + m0 + (lane >> 2);
    int r1 = r0 + 8;
    float d0 = g_dinv[r0], d1 = g_dinv[r1];
    int cbase = (lane & 3);
#pragma unroll
    for (int n = 0; n < 4; n++) {
        ((__half2*)g_h2s)[(size_t)r0 * 16 + n * 4 + cbase] =
            __floats2half2_rn(d0 * acc[n][0], d0 * acc[n][1]);
        ((__half2*)g_h2s)[(size_t)r1 * 16 + n * 4 + cbase] =
            __floats2half2_rn(d1 * acc[n][2], d1 * acc[n][3]);
    }
}

// ---------------- agg2: paired gather, fp16 pre-add (16 neighbors / iter) ------
// Warp = node, 8 groups x 4 lanes. Pair slots t+grp and t+8+grp.

__global__ void __launch_bounds__(256) k_agg2(const float* __restrict__ b2,
                                              float* __restrict__ out) {
    int node = blockIdx.x * 8 + (threadIdx.x >> 5);
    if (node >= N_NODES) return;
    const int lane = threadIdx.x & 31;
    const int grp  = lane >> 2;   // 0..7
    const int sub  = lane & 3;    // 0..3
    const uint4* h4 = (const uint4*)g_h2s;   // 4 uint4 per row
    int beg = g_offs[node], end = g_offs[node + 1];

    float acc[8];
#pragma unroll
    for (int q = 0; q < 8; q++) acc[q] = 0.0f;
    const uint4 zero4 = make_uint4(0u, 0u, 0u, 0u);

    for (int c = beg; c < end; c += 32) {
        int m = min(32, end - c);
        int idx = (c + lane < end) ? g_csr[c + lane] : 0;
        for (int t = 0; t < m; t += 16) {
            int s0 = t + grp;
            int s1 = t + 8 + grp;
            int j0 = __shfl_sync(0xffffffffu, idx, s0 & 31);
            int j1 = __shfl_sync(0xffffffffu, idx, s1 & 31);
            uint4 v0 = (s0 < m) ? h4[(size_t)j0 * 4 + sub] : zero4;
            uint4 v1 = (s1 < m) ? h4[(size_t)j1 * 4 + sub] : zero4;
            const __half2* a = (const __half2*)&v0;
            const __half2* b = (const __half2*)&v1;
#pragma unroll
            for (int q = 0; q < 4; q++) {
                float2 f = __half22float2(__hadd2(a[q], b[q]));
                acc[2 * q]     += f.x;
                acc[2 * q + 1] += f.y;
            }
        }
    }
#pragma unroll
    for (int q = 0; q < 8; q++) {
        acc[q] += __shfl_xor_sync(0xffffffffu, acc[q], 4);
        acc[q] += __shfl_xor_sync(0xffffffffu, acc[q], 8);
        acc[q] += __shfl_xor_sync(0xffffffffu, acc[q], 16);
    }
    if (lane < 4) {
        uint4 sv = h4[(size_t)node * 4 + lane];
        const __half2* shv = (const __half2*)&sv;
#pragma unroll
        for (int q = 0; q < 4; q++) {
            float2 f = __half22float2(shv[q]);
            acc[2 * q]     += f.x;
            acc[2 * q + 1] += f.y;
        }
        float di = g_dinv[node];
        const float4* b4 = (const float4*)b2;
        float4 bA = b4[lane * 2], bB = b4[lane * 2 + 1];
        float4 o0 = make_float4(bA.x + di * acc[0], bA.y + di * acc[1],
                                bA.z + di * acc[2], bA.w + di * acc[3]);
        float4 o1 = make_float4(bB.x + di * acc[4], bB.y + di * acc[5],
                                bB.z + di * acc[6], bB.w + di * acc[7]);
        ((float4*)out)[(size_t)node * 8 + lane * 2]     = o0;
        ((float4*)out)[(size_t)node * 8 + lane * 2 + 1] = o1;
    }
}

// ---------------- launch (single stream, 6 kernels) ----------------

extern "C" void kernel_launch(void* const* d_in, const int* in_sizes, int n_in,
                              void* d_out, int out_size) {
    const float* x   = (const float*)d_in[0];
    const int*   ei  = (const int*)d_in[1];
    const float* W1  = (const float*)d_in[2];
    const float* b1  = (const float*)d_in[3];
    const float* W2  = (const float*)d_in[4];
    const float* b2  = (const float*)d_in[5];
    float*       out = (float*)d_out;

    const int* src = ei;
    const int* dst = ei + N_EDGES;

    k_cnt       <<<(N_EDGES + 255) / 256, 256>>>(dst);
    k_scan      <<<N_SCAN_BLOCKS, SCAN_BLK>>>();
    k_fill_gemm1<<<GEMM1_BLOCKS + FILL_BLOCKS, 128>>>(x, W1, src, dst);
    k_agg1      <<<(N_NODES + 7) / 8, 256>>>(b1);
    k_gemm2     <<<N_NODES / 128, 256>>>(W2);
    k_agg2      <<<(N_NODES + 7) / 8, 256>>>(b2, out);
}